// round 15
// baseline (speedup 1.0000x reference)
#include <cuda_runtime.h>
#include <cuda_fp16.h>

#define NN 200000
#define EE 6400000
#define FIN 128

#define SCAN_T 256
#define SCAN_E 8
#define SCAN_CHUNK (SCAN_T * SCAN_E)                    // 2048
#define NB1 ((NN + SCAN_CHUNK - 1) / SCAN_CHUNK)        // 98

// Scratch (static __device__ — no allocation allowed; zero-initialized at load)
__device__ int   g_deg[NN];              // zeroed at end of each replay
__device__ float g_dinv[NN];
__device__ int   g_start[NN];
__device__ int   g_cursor[NN];
__device__ int   g_src[EE];
__device__ uint4 g_g1h[NN * 2];          // fp16 (x@W1)*dinv, 12 halves + 4 pad (32B/node)
__device__ uint4 g_uh[NN * 2];           // fp16 relu(layer1)*dinv
__device__ float g_v[NN * 12];           // fp32 layer-2 aggregate (pre-MLP)
__device__ int   g_bsum[NB1];

// ---------------------------------------------------------------------------
__device__ __forceinline__ bool is_idx64(const void* ei) {
    const int4* p = (const int4*)ei;
    int4 a = __ldg(p);
    int4 b = __ldg(p + 1);
    return ((a.y | a.w | b.y | b.w) == 0);
}

__device__ __forceinline__ unsigned pack2(float a, float b) {
    __half2 h = __floats2half2_rn(a, b);
    return *reinterpret_cast<unsigned*>(&h);
}
__device__ __forceinline__ void add2(float& a, float& b, unsigned u) {
    __half2 h = *reinterpret_cast<__half2*>(&u);
    float2 f = __half22float2(h);
    a += f.x; b += f.y;
}
__device__ __forceinline__ void acc12(float* acc, uint4 A, uint4 B) {
    add2(acc[0],  acc[1],  A.x);
    add2(acc[2],  acc[3],  A.y);
    add2(acc[4],  acc[5],  A.z);
    add2(acc[6],  acc[7],  A.w);
    add2(acc[8],  acc[9],  B.x);
    add2(acc[10], acc[11], B.y);
}
__device__ __forceinline__ float comp4(const float4& v, int kk) {
    return kk == 0 ? v.x : kk == 1 ? v.y : kk == 2 ? v.z : v.w;
}

// ---------------------------------------------------------------------------
// Degree histogram over targets (col half only; fire-and-forget atomics).
// 8 edges/thread.
__global__ void k_deg(const void* __restrict__ ei, int ecnt) {
    int t  = blockIdx.x * blockDim.x + threadIdx.x;
    int e0 = t * 8;
    if (e0 >= ecnt) return;
    bool i64 = is_idx64(ei);
    if (e0 + 7 < ecnt) {
        int c[8];
        if (i64) {
            const longlong2* pc = (const longlong2*)((const long long*)ei + ecnt + e0);
            #pragma unroll
            for (int q = 0; q < 4; ++q) {
                longlong2 cv = __ldcs(pc + q);
                c[q * 2] = (int)cv.x; c[q * 2 + 1] = (int)cv.y;
            }
        } else {
            const int4* pc = (const int4*)((const int*)ei + ecnt + e0);
            int4 a = __ldcs(pc), b = __ldcs(pc + 1);
            c[0] = a.x; c[1] = a.y; c[2] = a.z; c[3] = a.w;
            c[4] = b.x; c[5] = b.y; c[6] = b.z; c[7] = b.w;
        }
        #pragma unroll
        for (int q = 0; q < 8; ++q) atomicAdd(&g_deg[c[q]], 1);
    } else {
        for (int e = e0; e < ecnt; ++e) {
            int cc = i64 ? (int)((const long long*)ei)[(long long)ecnt + e]
                         : ((const int*)ei)[ecnt + e];
            atomicAdd(&g_deg[cc], 1);
        }
    }
}

// ---------------------------------------------------------------------------
// Scan pass 1: per-chunk exclusive scan + chunk sums.
__global__ void k_scan1(int n) {
    __shared__ int ts[SCAN_T];
    int base = blockIdx.x * SCAN_CHUNK + threadIdx.x * SCAN_E;
    int v[SCAN_E];
    int sum = 0;
    #pragma unroll
    for (int j = 0; j < SCAN_E; ++j) {
        int idx = base + j;
        v[j] = (idx < n) ? g_deg[idx] : 0;
        sum += v[j];
    }
    ts[threadIdx.x] = sum;
    __syncthreads();
    for (int off = 1; off < SCAN_T; off <<= 1) {
        int t = (threadIdx.x >= off) ? ts[threadIdx.x - off] : 0;
        __syncthreads();
        ts[threadIdx.x] += t;
        __syncthreads();
    }
    int run = ts[threadIdx.x] - sum;
    if (threadIdx.x == SCAN_T - 1) g_bsum[blockIdx.x] = ts[SCAN_T - 1];
    #pragma unroll
    for (int j = 0; j < SCAN_E; ++j) {
        int idx = base + j;
        if (idx < n) g_start[idx] = run;
        run += v[j];
    }
}

// Scan pass 2+3 merged.
__global__ void k_scan23(int n) {
    __shared__ int ts[SCAN_T];
    int t = threadIdx.x;
    int v = (t < NB1) ? g_bsum[t] : 0;
    ts[t] = v;
    __syncthreads();
    for (int off = 1; off < SCAN_T; off <<= 1) {
        int w = (t >= off) ? ts[t - off] : 0;
        __syncthreads();
        ts[t] += w;
        __syncthreads();
    }

    int i = blockIdx.x * blockDim.x + threadIdx.x;
    if (i >= n) return;
    int chunk = i / SCAN_CHUNK;
    int base = (chunk == 0) ? 0 : ts[chunk - 1];
    int s = g_start[i] + base;
    g_start[i]  = s;
    g_cursor[i] = s;
    g_dinv[i]   = rsqrtf((float)(g_deg[i] + 1));
}

// ---------------------------------------------------------------------------
// Fused: GEMM1 at 1 node/thread (blocks [0, nb_gemm)) + CSR fill at 8
// edges/thread (remaining blocks). Lower regs -> higher fill occupancy.
__global__ void __launch_bounds__(256) k_fill_gemm(
        const void* __restrict__ ei, int ecnt,
        const float* __restrict__ x, const float* __restrict__ W1,
        int n, int nb_gemm) {
    __shared__ float Ws[FIN * 12];

    if (blockIdx.x < nb_gemm) {
        // ---- GEMM1: g1h[n] = fp16( dinv[n] * (x[n] @ W1) ), 1 node/thread --
        for (int i = threadIdx.x; i < FIN * 12; i += blockDim.x) Ws[i] = W1[i];
        __syncthreads();

        int node = blockIdx.x * blockDim.x + threadIdx.x;
        if (node >= n) return;

        float a0[12];
        #pragma unroll
        for (int j = 0; j < 12; ++j) a0[j] = 0.0f;

        const float4* xr = (const float4*)x + (size_t)node * (FIN / 4);

        #pragma unroll 4
        for (int k4 = 0; k4 < FIN / 4; ++k4) {
            float4 a = __ldcs(xr + k4);
            #pragma unroll
            for (int kk = 0; kk < 4; ++kk) {
                const float4* wp = (const float4*)(Ws + (k4 * 4 + kk) * 12);
                float4 w0 = wp[0], w1 = wp[1], w2 = wp[2];
                float xa = comp4(a, kk);
                a0[0]  += xa * w0.x; a0[1]  += xa * w0.y; a0[2]  += xa * w0.z; a0[3]  += xa * w0.w;
                a0[4]  += xa * w1.x; a0[5]  += xa * w1.y; a0[6]  += xa * w1.z; a0[7]  += xa * w1.w;
                a0[8]  += xa * w2.x; a0[9]  += xa * w2.y; a0[10] += xa * w2.z; a0[11] += xa * w2.w;
            }
        }

        float dn = g_dinv[node];
        uint4 A, B;
        A.x = pack2(a0[0] * dn, a0[1] * dn);
        A.y = pack2(a0[2] * dn, a0[3] * dn);
        A.z = pack2(a0[4] * dn, a0[5] * dn);
        A.w = pack2(a0[6] * dn, a0[7] * dn);
        B.x = pack2(a0[8] * dn, a0[9] * dn);
        B.y = pack2(a0[10] * dn, a0[11] * dn);
        B.z = 0; B.w = 0;
        g_g1h[(size_t)node * 2]     = A;
        g_g1h[(size_t)node * 2 + 1] = B;
    } else {
        // ---- CSR fill: 8 edges/thread; slot = cursor[col]++ ; src[slot]=row
        int t  = (blockIdx.x - nb_gemm) * blockDim.x + threadIdx.x;
        int e0 = t * 8;
        if (e0 >= ecnt) return;
        bool i64 = is_idx64(ei);
        if (e0 + 7 < ecnt) {
            int r[8], c[8];
            if (i64) {
                const longlong2* pr = (const longlong2*)((const long long*)ei + e0);
                const longlong2* pc = (const longlong2*)((const long long*)ei + ecnt + e0);
                #pragma unroll
                for (int q = 0; q < 4; ++q) {
                    longlong2 rv = __ldcs(pr + q);
                    longlong2 cv = __ldcs(pc + q);
                    r[q * 2] = (int)rv.x; r[q * 2 + 1] = (int)rv.y;
                    c[q * 2] = (int)cv.x; c[q * 2 + 1] = (int)cv.y;
                }
            } else {
                const int4* pr = (const int4*)((const int*)ei + e0);
                const int4* pc = (const int4*)((const int*)ei + ecnt + e0);
                int4 ra = __ldcs(pr), rb = __ldcs(pr + 1);
                int4 ca = __ldcs(pc), cb = __ldcs(pc + 1);
                r[0] = ra.x; r[1] = ra.y; r[2] = ra.z; r[3] = ra.w;
                r[4] = rb.x; r[5] = rb.y; r[6] = rb.z; r[7] = rb.w;
                c[0] = ca.x; c[1] = ca.y; c[2] = ca.z; c[3] = ca.w;
                c[4] = cb.x; c[5] = cb.y; c[6] = cb.z; c[7] = cb.w;
            }
            int s[8];
            #pragma unroll
            for (int q = 0; q < 8; ++q) s[q] = atomicAdd(&g_cursor[c[q]], 1);
            #pragma unroll
            for (int q = 0; q < 8; ++q) g_src[s[q]] = r[q];
        } else {
            for (int e = e0; e < ecnt; ++e) {
                int rr, cc;
                if (i64) {
                    const long long* p = (const long long*)ei;
                    rr = (int)p[e]; cc = (int)p[(long long)ecnt + e];
                } else {
                    const int* p = (const int*)ei;
                    rr = p[e]; cc = p[ecnt + e];
                }
                int sl = atomicAdd(&g_cursor[cc], 1);
                g_src[sl] = rr;
            }
        }
    }
}

// ---------------------------------------------------------------------------
// 4-lane cooperative gather, 4 edges/lane in flight. All lanes converged.
__device__ __forceinline__ void gather12_c4(const uint4* __restrict__ feat,
                                            int node, int lane, float* acc) {
    int s = g_start[node];
    int end = s + g_deg[node];

    #pragma unroll
    for (int j = 0; j < 12; ++j) acc[j] = 0.0f;

    int i = s + lane;
    for (; i + 12 < end; i += 16) {
        int r0 = __ldg(&g_src[i]);
        int r1 = __ldg(&g_src[i + 4]);
        int r2 = __ldg(&g_src[i + 8]);
        int r3 = __ldg(&g_src[i + 12]);
        uint4 A0 = __ldg(feat + (size_t)r0 * 2), B0 = __ldg(feat + (size_t)r0 * 2 + 1);
        uint4 A1 = __ldg(feat + (size_t)r1 * 2), B1 = __ldg(feat + (size_t)r1 * 2 + 1);
        uint4 A2 = __ldg(feat + (size_t)r2 * 2), B2 = __ldg(feat + (size_t)r2 * 2 + 1);
        uint4 A3 = __ldg(feat + (size_t)r3 * 2), B3 = __ldg(feat + (size_t)r3 * 2 + 1);
        acc12(acc, A0, B0);
        acc12(acc, A1, B1);
        acc12(acc, A2, B2);
        acc12(acc, A3, B3);
    }
    for (; i < end; i += 4) {
        int r0 = __ldg(&g_src[i]);
        uint4 A0 = __ldg(feat + (size_t)r0 * 2), B0 = __ldg(feat + (size_t)r0 * 2 + 1);
        acc12(acc, A0, B0);
    }
    if (lane == 0) {
        uint4 A = feat[(size_t)node * 2];
        uint4 B = feat[(size_t)node * 2 + 1];
        acc12(acc, A, B);
    }
    #pragma unroll
    for (int off = 1; off <= 2; off <<= 1) {
        #pragma unroll
        for (int j = 0; j < 12; ++j)
            acc[j] += __shfl_xor_sync(0xffffffffu, acc[j], off);
    }
}

// Gather layer 1 + epilogue: u = fp16( relu(dinv*sum + b1) * dinv )
__global__ void k_gather_u(const float* __restrict__ b1v, int n) {
    __shared__ float bs[12];
    if (threadIdx.x < 12) bs[threadIdx.x] = b1v[threadIdx.x];
    __syncthreads();

    int g = blockIdx.x * blockDim.x + threadIdx.x;
    int node = g >> 2;
    int lane = g & 3;
    bool valid = (node < n);
    if (node >= n) node = n - 1;

    float acc[12];
    gather12_c4(g_g1h, node, lane, acc);

    if (valid && lane == 0) {
        float dn = g_dinv[node];
        float u[12];
        #pragma unroll
        for (int j = 0; j < 12; ++j)
            u[j] = fmaxf(dn * acc[j] + bs[j], 0.0f) * dn;
        uint4 A, B;
        A.x = pack2(u[0], u[1]);
        A.y = pack2(u[2], u[3]);
        A.z = pack2(u[4], u[5]);
        A.w = pack2(u[6], u[7]);
        B.x = pack2(u[8], u[9]);
        B.y = pack2(u[10], u[11]);
        B.z = 0; B.w = 0;
        g_uh[(size_t)node * 2]     = A;
        g_uh[(size_t)node * 2 + 1] = B;
    }
}

// Gather layer 2: v = dinv * (sum_in u + u[self])   (lean; MLP separate)
__global__ void k_gather_v(int n) {
    int g = blockIdx.x * blockDim.x + threadIdx.x;
    int node = g >> 2;
    int lane = g & 3;
    bool valid = (node < n);
    if (node >= n) node = n - 1;

    float acc[12];
    gather12_c4(g_uh, node, lane, acc);

    if (valid && lane == 0) {
        float dn = g_dinv[node];
        float4* out4 = (float4*)g_v + (size_t)node * 3;
        out4[0] = make_float4(dn * acc[0], dn * acc[1], dn * acc[2],  dn * acc[3]);
        out4[1] = make_float4(dn * acc[4], dn * acc[5], dn * acc[6],  dn * acc[7]);
        out4[2] = make_float4(dn * acc[8], dn * acc[9], dn * acc[10], dn * acc[11]);
    }
}

// ---------------------------------------------------------------------------
// MLP epilogue + re-zero g_deg for the next replay.
__global__ void k_mlp(const float* __restrict__ W2, const float* __restrict__ b2v,
                      const float* __restrict__ Wf1, const float* __restrict__ bf1,
                      const float* __restrict__ Wf2, const float* __restrict__ bf2,
                      float* __restrict__ out, int n) {
    __shared__ float W2s[12 * 24];
    __shared__ float Wf1s[24 * 32];
    __shared__ float Wf2s[32 * 2];
    __shared__ float b2s[24], bf1s[32], bf2s[2];
    for (int i = threadIdx.x; i < 12 * 24; i += blockDim.x) W2s[i] = W2[i];
    for (int i = threadIdx.x; i < 24 * 32; i += blockDim.x) Wf1s[i] = Wf1[i];
    if (threadIdx.x < 64) Wf2s[threadIdx.x] = Wf2[threadIdx.x];
    if (threadIdx.x < 24) b2s[threadIdx.x] = b2v[threadIdx.x];
    if (threadIdx.x < 32) bf1s[threadIdx.x] = bf1[threadIdx.x];
    if (threadIdx.x < 2)  bf2s[threadIdx.x] = bf2[threadIdx.x];
    __syncthreads();

    int node = blockIdx.x * blockDim.x + threadIdx.x;
    if (node >= n) return;

    g_deg[node] = 0;   // reset for next replay

    const float4* v4 = (const float4*)g_v + (size_t)node * 3;
    float4 v0 = v4[0], v1 = v4[1], v2 = v4[2];
    float v[12] = { v0.x, v0.y, v0.z, v0.w, v1.x, v1.y, v1.z, v1.w, v2.x, v2.y, v2.z, v2.w };

    float h2[24];
    #pragma unroll
    for (int j2 = 0; j2 < 24; ++j2) h2[j2] = b2s[j2];
    #pragma unroll
    for (int j = 0; j < 12; ++j) {
        float hv = v[j];
        const float* wr = W2s + j * 24;
        #pragma unroll
        for (int j2 = 0; j2 < 24; ++j2) h2[j2] += hv * wr[j2];
    }
    #pragma unroll
    for (int j2 = 0; j2 < 24; ++j2) h2[j2] = fmaxf(h2[j2], 0.0f);

    float h3[32];
    #pragma unroll
    for (int o = 0; o < 32; ++o) h3[o] = bf1s[o];
    #pragma unroll
    for (int j = 0; j < 24; ++j) {
        float hv = h2[j];
        const float* wr = Wf1s + j * 32;
        #pragma unroll
        for (int o = 0; o < 32; ++o) h3[o] += hv * wr[o];
    }
    #pragma unroll
    for (int o = 0; o < 32; ++o) h3[o] = fmaxf(h3[o], 0.0f);

    float o0 = bf2s[0], o1 = bf2s[1];
    #pragma unroll
    for (int o = 0; o < 32; ++o) {
        o0 += h3[o] * Wf2s[o * 2 + 0];
        o1 += h3[o] * Wf2s[o * 2 + 1];
    }
    ((float2*)out)[node] = make_float2(o0, o1);
}

// ---------------------------------------------------------------------------
extern "C" void kernel_launch(void* const* d_in, const int* in_sizes, int n_in,
                              void* d_out, int out_size) {
    const float* x   = (const float*)d_in[0];
    const void*  ei  = d_in[1];
    const float* W1  = (const float*)d_in[2];
    const float* b1  = (const float*)d_in[3];
    const float* W2  = (const float*)d_in[4];
    const float* b2  = (const float*)d_in[5];
    const float* Wf1 = (const float*)d_in[6];
    const float* bf1 = (const float*)d_in[7];
    const float* Wf2 = (const float*)d_in[8];
    const float* bf2 = (const float*)d_in[9];
    float* out = (float*)d_out;

    const int n = in_sizes[0] / FIN;       // 200000
    const int e = in_sizes[1] / 2;         // 6400000
    const int eocts = (e + 7) / 8;

    const int T = 256;
    const int nb_gemm = (n + T - 1) / T;                // 782 (1 node/thread)
    const int nb_fill = (eocts + T - 1) / T;            // 3125

    k_deg<<<(eocts + T - 1) / T, T>>>(ei, e);
    k_scan1<<<NB1, SCAN_T>>>(n);
    k_scan23<<<(n + T - 1) / T, T>>>(n);
    k_fill_gemm<<<nb_gemm + nb_fill, T>>>(ei, e, x, W1, n, nb_gemm);
    k_gather_u<<<(n * 4 + T - 1) / T, T>>>(b1, n);
    k_gather_v<<<(n * 4 + T - 1) / T, T>>>(n);
    k_mlp<<<(n + T - 1) / T, T>>>(W2, b2, Wf1, bf1, Wf2, bf2, out, n);
}

// round 16
// speedup vs baseline: 1.4366x; 1.4366x over previous
#include <cuda_runtime.h>
#include <cuda_fp16.h>

#define NN 200000
#define EE 6400000
#define FIN 128

#define SCAN_T 256
#define SCAN_E 8
#define SCAN_CHUNK (SCAN_T * SCAN_E)                    // 2048
#define NB1 ((NN + SCAN_CHUNK - 1) / SCAN_CHUNK)        // 98

// Scratch (static __device__ — no allocation allowed; zero-initialized at load)
__device__ int   g_deg[NN];              // zeroed at end of each replay
__device__ float g_dinv[NN];
__device__ int   g_start[NN];
__device__ int   g_cursor[NN];
__device__ int   g_src[EE];
__device__ uint4 g_g1h[NN * 2];          // fp16 (x@W1)*dinv, 12 halves + 4 pad (32B/node)
__device__ uint4 g_uh[NN * 2];           // fp16 relu(layer1)*dinv
__device__ float g_v[NN * 12];           // fp32 layer-2 aggregate (pre-MLP)
__device__ int   g_bsum[NB1];

// ---------------------------------------------------------------------------
__device__ __forceinline__ bool is_idx64(const void* ei) {
    const int4* p = (const int4*)ei;
    int4 a = __ldg(p);
    int4 b = __ldg(p + 1);
    return ((a.y | a.w | b.y | b.w) == 0);
}

__device__ __forceinline__ unsigned pack2(float a, float b) {
    __half2 h = __floats2half2_rn(a, b);
    return *reinterpret_cast<unsigned*>(&h);
}
__device__ __forceinline__ void add2(float& a, float& b, unsigned u) {
    __half2 h = *reinterpret_cast<__half2*>(&u);
    float2 f = __half22float2(h);
    a += f.x; b += f.y;
}
__device__ __forceinline__ void acc12(float* acc, uint4 A, uint4 B) {
    add2(acc[0],  acc[1],  A.x);
    add2(acc[2],  acc[3],  A.y);
    add2(acc[4],  acc[5],  A.z);
    add2(acc[6],  acc[7],  A.w);
    add2(acc[8],  acc[9],  B.x);
    add2(acc[10], acc[11], B.y);
}
__device__ __forceinline__ float comp4(const float4& v, int kk) {
    return kk == 0 ? v.x : kk == 1 ? v.y : kk == 2 ? v.z : v.w;
}

// ---------------------------------------------------------------------------
// Degree histogram over targets (col half only; fire-and-forget atomics).
__global__ void k_deg(const void* __restrict__ ei, int ecnt) {
    int t  = blockIdx.x * blockDim.x + threadIdx.x;
    int e0 = t * 4;
    if (e0 >= ecnt) return;
    bool i64 = is_idx64(ei);
    if (e0 + 3 < ecnt) {
        int c0, c1, c2, c3;
        if (i64) {
            const longlong2* pc = (const longlong2*)((const long long*)ei + ecnt + e0);
            longlong2 c01 = __ldcs(pc), c23 = __ldcs(pc + 1);
            c0 = (int)c01.x; c1 = (int)c01.y; c2 = (int)c23.x; c3 = (int)c23.y;
        } else {
            int4 cv = __ldcs((const int4*)((const int*)ei + ecnt + e0));
            c0 = cv.x; c1 = cv.y; c2 = cv.z; c3 = cv.w;
        }
        atomicAdd(&g_deg[c0], 1);
        atomicAdd(&g_deg[c1], 1);
        atomicAdd(&g_deg[c2], 1);
        atomicAdd(&g_deg[c3], 1);
    } else {
        for (int e = e0; e < ecnt; ++e) {
            int cc = i64 ? (int)((const long long*)ei)[(long long)ecnt + e]
                         : ((const int*)ei)[ecnt + e];
            atomicAdd(&g_deg[cc], 1);
        }
    }
}

// ---------------------------------------------------------------------------
// Scan pass 1: per-chunk exclusive scan + chunk sums.
__global__ void k_scan1(int n) {
    __shared__ int ts[SCAN_T];
    int base = blockIdx.x * SCAN_CHUNK + threadIdx.x * SCAN_E;
    int v[SCAN_E];
    int sum = 0;
    #pragma unroll
    for (int j = 0; j < SCAN_E; ++j) {
        int idx = base + j;
        v[j] = (idx < n) ? g_deg[idx] : 0;
        sum += v[j];
    }
    ts[threadIdx.x] = sum;
    __syncthreads();
    for (int off = 1; off < SCAN_T; off <<= 1) {
        int t = (threadIdx.x >= off) ? ts[threadIdx.x - off] : 0;
        __syncthreads();
        ts[threadIdx.x] += t;
        __syncthreads();
    }
    int run = ts[threadIdx.x] - sum;
    if (threadIdx.x == SCAN_T - 1) g_bsum[blockIdx.x] = ts[SCAN_T - 1];
    #pragma unroll
    for (int j = 0; j < SCAN_E; ++j) {
        int idx = base + j;
        if (idx < n) g_start[idx] = run;
        run += v[j];
    }
}

// Scan pass 2+3 merged: redundant block-scan of chunk sums, then finalize.
__global__ void k_scan23(int n) {
    __shared__ int ts[SCAN_T];
    int t = threadIdx.x;
    int v = (t < NB1) ? g_bsum[t] : 0;
    ts[t] = v;
    __syncthreads();
    for (int off = 1; off < SCAN_T; off <<= 1) {
        int w = (t >= off) ? ts[t - off] : 0;
        __syncthreads();
        ts[t] += w;
        __syncthreads();
    }

    int i = blockIdx.x * blockDim.x + threadIdx.x;
    if (i >= n) return;
    int chunk = i / SCAN_CHUNK;
    int base = (chunk == 0) ? 0 : ts[chunk - 1];
    int s = g_start[i] + base;
    g_start[i]  = s;
    g_cursor[i] = s;
    g_dinv[i]   = rsqrtf((float)(g_deg[i] + 1));
}

// ---------------------------------------------------------------------------
// Fused: GEMM1 at 1 node/thread (blocks [0, nb_gemm)) + CSR fill at 4
// edges/thread (remaining blocks). No launch_bounds — natural regs, no spill.
__global__ void k_fill_gemm(const void* __restrict__ ei, int ecnt,
                            const float* __restrict__ x, const float* __restrict__ W1,
                            int n, int nb_gemm) {
    __shared__ float Ws[FIN * 12];

    if (blockIdx.x < nb_gemm) {
        // ---- GEMM1: g1h[n] = fp16( dinv[n] * (x[n] @ W1) ), 1 node/thread --
        for (int i = threadIdx.x; i < FIN * 12; i += blockDim.x) Ws[i] = W1[i];
        __syncthreads();

        int node = blockIdx.x * blockDim.x + threadIdx.x;
        if (node >= n) return;

        float a0[12];
        #pragma unroll
        for (int j = 0; j < 12; ++j) a0[j] = 0.0f;

        const float4* xr = (const float4*)x + (size_t)node * (FIN / 4);

        #pragma unroll 4
        for (int k4 = 0; k4 < FIN / 4; ++k4) {
            float4 a = __ldcs(xr + k4);
            #pragma unroll
            for (int kk = 0; kk < 4; ++kk) {
                const float4* wp = (const float4*)(Ws + (k4 * 4 + kk) * 12);
                float4 w0 = wp[0], w1 = wp[1], w2 = wp[2];
                float xa = comp4(a, kk);
                a0[0]  += xa * w0.x; a0[1]  += xa * w0.y; a0[2]  += xa * w0.z; a0[3]  += xa * w0.w;
                a0[4]  += xa * w1.x; a0[5]  += xa * w1.y; a0[6]  += xa * w1.z; a0[7]  += xa * w1.w;
                a0[8]  += xa * w2.x; a0[9]  += xa * w2.y; a0[10] += xa * w2.z; a0[11] += xa * w2.w;
            }
        }

        float dn = g_dinv[node];
        uint4 A, B;
        A.x = pack2(a0[0] * dn, a0[1] * dn);
        A.y = pack2(a0[2] * dn, a0[3] * dn);
        A.z = pack2(a0[4] * dn, a0[5] * dn);
        A.w = pack2(a0[6] * dn, a0[7] * dn);
        B.x = pack2(a0[8] * dn, a0[9] * dn);
        B.y = pack2(a0[10] * dn, a0[11] * dn);
        B.z = 0; B.w = 0;
        g_g1h[(size_t)node * 2]     = A;
        g_g1h[(size_t)node * 2 + 1] = B;
    } else {
        // ---- CSR fill: 4 edges/thread; slot = cursor[col]++ ; src[slot]=row
        int t  = (blockIdx.x - nb_gemm) * blockDim.x + threadIdx.x;
        int e0 = t * 4;
        if (e0 >= ecnt) return;
        bool i64 = is_idx64(ei);
        if (e0 + 3 < ecnt) {
            int r0, r1, r2, r3, c0, c1, c2, c3;
            if (i64) {
                const longlong2* pr = (const longlong2*)((const long long*)ei + e0);
                const longlong2* pc = (const longlong2*)((const long long*)ei + ecnt + e0);
                longlong2 r01 = __ldcs(pr), r23 = __ldcs(pr + 1);
                longlong2 c01 = __ldcs(pc), c23 = __ldcs(pc + 1);
                r0 = (int)r01.x; r1 = (int)r01.y; r2 = (int)r23.x; r3 = (int)r23.y;
                c0 = (int)c01.x; c1 = (int)c01.y; c2 = (int)c23.x; c3 = (int)c23.y;
            } else {
                int4 rv = __ldcs((const int4*)((const int*)ei + e0));
                int4 cv = __ldcs((const int4*)((const int*)ei + ecnt + e0));
                r0 = rv.x; r1 = rv.y; r2 = rv.z; r3 = rv.w;
                c0 = cv.x; c1 = cv.y; c2 = cv.z; c3 = cv.w;
            }
            int s0 = atomicAdd(&g_cursor[c0], 1);
            int s1 = atomicAdd(&g_cursor[c1], 1);
            int s2 = atomicAdd(&g_cursor[c2], 1);
            int s3 = atomicAdd(&g_cursor[c3], 1);
            g_src[s0] = r0;
            g_src[s1] = r1;
            g_src[s2] = r2;
            g_src[s3] = r3;
        } else {
            for (int e = e0; e < ecnt; ++e) {
                int rr, cc;
                if (i64) {
                    const long long* p = (const long long*)ei;
                    rr = (int)p[e]; cc = (int)p[(long long)ecnt + e];
                } else {
                    const int* p = (const int*)ei;
                    rr = p[e]; cc = p[ecnt + e];
                }
                int s = atomicAdd(&g_cursor[cc], 1);
                g_src[s] = rr;
            }
        }
    }
}

// ---------------------------------------------------------------------------
// 4-lane cooperative gather, 2 edges/lane in flight. All lanes converged.
__device__ __forceinline__ void gather12_c4(const uint4* __restrict__ feat,
                                            int node, int lane, float* acc) {
    int s = g_start[node];
    int end = s + g_deg[node];

    #pragma unroll
    for (int j = 0; j < 12; ++j) acc[j] = 0.0f;

    int i = s + lane;
    for (; i + 4 < end; i += 8) {
        int r0 = __ldg(&g_src[i]);
        int r1 = __ldg(&g_src[i + 4]);
        uint4 A0 = __ldg(feat + (size_t)r0 * 2), B0 = __ldg(feat + (size_t)r0 * 2 + 1);
        uint4 A1 = __ldg(feat + (size_t)r1 * 2), B1 = __ldg(feat + (size_t)r1 * 2 + 1);
        acc12(acc, A0, B0);
        acc12(acc, A1, B1);
    }
    if (i < end) {
        int r0 = __ldg(&g_src[i]);
        uint4 A0 = __ldg(feat + (size_t)r0 * 2), B0 = __ldg(feat + (size_t)r0 * 2 + 1);
        acc12(acc, A0, B0);
    }
    if (lane == 0) {
        uint4 A = feat[(size_t)node * 2];
        uint4 B = feat[(size_t)node * 2 + 1];
        acc12(acc, A, B);
    }
    #pragma unroll
    for (int off = 1; off <= 2; off <<= 1) {
        #pragma unroll
        for (int j = 0; j < 12; ++j)
            acc[j] += __shfl_xor_sync(0xffffffffu, acc[j], off);
    }
}

// Gather layer 1 + epilogue: u = fp16( relu(dinv*sum + b1) * dinv )
__global__ void k_gather_u(const float* __restrict__ b1v, int n) {
    __shared__ float bs[12];
    if (threadIdx.x < 12) bs[threadIdx.x] = b1v[threadIdx.x];
    __syncthreads();

    int g = blockIdx.x * blockDim.x + threadIdx.x;
    int node = g >> 2;
    int lane = g & 3;
    bool valid = (node < n);
    if (node >= n) node = n - 1;

    float acc[12];
    gather12_c4(g_g1h, node, lane, acc);

    if (valid && lane == 0) {
        float dn = g_dinv[node];
        float u[12];
        #pragma unroll
        for (int j = 0; j < 12; ++j)
            u[j] = fmaxf(dn * acc[j] + bs[j], 0.0f) * dn;
        uint4 A, B;
        A.x = pack2(u[0], u[1]);
        A.y = pack2(u[2], u[3]);
        A.z = pack2(u[4], u[5]);
        A.w = pack2(u[6], u[7]);
        B.x = pack2(u[8], u[9]);
        B.y = pack2(u[10], u[11]);
        B.z = 0; B.w = 0;
        g_uh[(size_t)node * 2]     = A;
        g_uh[(size_t)node * 2 + 1] = B;
    }
}

// Gather layer 2: v = dinv * (sum_in u + u[self])   (lean; MLP separate)
__global__ void k_gather_v(int n) {
    int g = blockIdx.x * blockDim.x + threadIdx.x;
    int node = g >> 2;
    int lane = g & 3;
    bool valid = (node < n);
    if (node >= n) node = n - 1;

    float acc[12];
    gather12_c4(g_uh, node, lane, acc);

    if (valid && lane == 0) {
        float dn = g_dinv[node];
        float4* out4 = (float4*)g_v + (size_t)node * 3;
        out4[0] = make_float4(dn * acc[0], dn * acc[1], dn * acc[2],  dn * acc[3]);
        out4[1] = make_float4(dn * acc[4], dn * acc[5], dn * acc[6],  dn * acc[7]);
        out4[2] = make_float4(dn * acc[8], dn * acc[9], dn * acc[10], dn * acc[11]);
    }
}

// ---------------------------------------------------------------------------
// MLP epilogue + re-zero g_deg for the next replay.
__global__ void k_mlp(const float* __restrict__ W2, const float* __restrict__ b2v,
                      const float* __restrict__ Wf1, const float* __restrict__ bf1,
                      const float* __restrict__ Wf2, const float* __restrict__ bf2,
                      float* __restrict__ out, int n) {
    __shared__ float W2s[12 * 24];
    __shared__ float Wf1s[24 * 32];
    __shared__ float Wf2s[32 * 2];
    __shared__ float b2s[24], bf1s[32], bf2s[2];
    for (int i = threadIdx.x; i < 12 * 24; i += blockDim.x) W2s[i] = W2[i];
    for (int i = threadIdx.x; i < 24 * 32; i += blockDim.x) Wf1s[i] = Wf1[i];
    if (threadIdx.x < 64) Wf2s[threadIdx.x] = Wf2[threadIdx.x];
    if (threadIdx.x < 24) b2s[threadIdx.x] = b2v[threadIdx.x];
    if (threadIdx.x < 32) bf1s[threadIdx.x] = bf1[threadIdx.x];
    if (threadIdx.x < 2)  bf2s[threadIdx.x] = bf2[threadIdx.x];
    __syncthreads();

    int node = blockIdx.x * blockDim.x + threadIdx.x;
    if (node >= n) return;

    g_deg[node] = 0;   // reset for next replay

    const float4* v4 = (const float4*)g_v + (size_t)node * 3;
    float4 v0 = v4[0], v1 = v4[1], v2 = v4[2];
    float v[12] = { v0.x, v0.y, v0.z, v0.w, v1.x, v1.y, v1.z, v1.w, v2.x, v2.y, v2.z, v2.w };

    float h2[24];
    #pragma unroll
    for (int j2 = 0; j2 < 24; ++j2) h2[j2] = b2s[j2];
    #pragma unroll
    for (int j = 0; j < 12; ++j) {
        float hv = v[j];
        const float* wr = W2s + j * 24;
        #pragma unroll
        for (int j2 = 0; j2 < 24; ++j2) h2[j2] += hv * wr[j2];
    }
    #pragma unroll
    for (int j2 = 0; j2 < 24; ++j2) h2[j2] = fmaxf(h2[j2], 0.0f);

    float h3[32];
    #pragma unroll
    for (int o = 0; o < 32; ++o) h3[o] = bf1s[o];
    #pragma unroll
    for (int j = 0; j < 24; ++j) {
        float hv = h2[j];
        const float* wr = Wf1s + j * 32;
        #pragma unroll
        for (int o = 0; o < 32; ++o) h3[o] += hv * wr[o];
    }
    #pragma unroll
    for (int o = 0; o < 32; ++o) h3[o] = fmaxf(h3[o], 0.0f);

    float o0 = bf2s[0], o1 = bf2s[1];
    #pragma unroll
    for (int o = 0; o < 32; ++o) {
        o0 += h3[o] * Wf2s[o * 2 + 0];
        o1 += h3[o] * Wf2s[o * 2 + 1];
    }
    ((float2*)out)[node] = make_float2(o0, o1);
}

// ---------------------------------------------------------------------------
extern "C" void kernel_launch(void* const* d_in, const int* in_sizes, int n_in,
                              void* d_out, int out_size) {
    const float* x   = (const float*)d_in[0];
    const void*  ei  = d_in[1];
    const float* W1  = (const float*)d_in[2];
    const float* b1  = (const float*)d_in[3];
    const float* W2  = (const float*)d_in[4];
    const float* b2  = (const float*)d_in[5];
    const float* Wf1 = (const float*)d_in[6];
    const float* bf1 = (const float*)d_in[7];
    const float* Wf2 = (const float*)d_in[8];
    const float* bf2 = (const float*)d_in[9];
    float* out = (float*)d_out;

    const int n = in_sizes[0] / FIN;       // 200000
    const int e = in_sizes[1] / 2;         // 6400000
    const int equads = (e + 3) / 4;

    const int T = 256;
    const int nb_gemm = (n + T - 1) / T;                // 782 (1 node/thread)
    const int nb_fill = (equads + T - 1) / T;           // 6250

    k_deg<<<(equads + T - 1) / T, T>>>(ei, e);
    k_scan1<<<NB1, SCAN_T>>>(n);
    k_scan23<<<(n + T - 1) / T, T>>>(n);
    k_fill_gemm<<<nb_gemm + nb_fill, T>>>(ei, e, x, W1, n, nb_gemm);
    k_gather_u<<<(n * 4 + T - 1) / T, T>>>(b1, n);
    k_gather_v<<<(n * 4 + T - 1) / T, T>>>(n);
    k_mlp<<<(n + T - 1) / T, T>>>(W2, b2, Wf1, bf1, Wf2, bf2, out, n);
}